// round 15
// baseline (speedup 1.0000x reference)
#include <cuda_runtime.h>
#include <cuda_bf16.h>
#include <math.h>

#define NN 100000
#define EE 3200000
#define BN_C 256
#define EPS 1e-5f

// ---------------- scratch (device globals; no allocation allowed) -------------
__device__ float g_bufA[(size_t)NN * 512];
__device__ float g_bufB[(size_t)NN * 512];
__device__ int   g_rowptr[NN + 1];
__device__ int   g_cursor[NN];
__device__ int   g_counts[NN];
__device__ int   g_bsums[128];
__device__ int   g_bsums_ex[128];
__device__ int   g_csr_col[EE];
__device__ float g_csr_val[EE];
__device__ float g_sum[BN_C];
__device__ float g_sumsq[BN_C];
__device__ float g_mean[BN_C];
__device__ float g_inv[BN_C];

static inline int cdiv(int a, int b) { return (a + b - 1) / b; }

// ---------------- CSR build ---------------------------------------------------
__global__ void zero_counts_k(int* counts, int n) {
    for (int i = blockIdx.x * blockDim.x + threadIdx.x; i < n; i += gridDim.x * blockDim.x)
        counts[i] = 0;
}

__global__ void hist_k(const int* __restrict__ rows, int* counts, int e) {
    for (int i = blockIdx.x * blockDim.x + threadIdx.x; i < e; i += gridDim.x * blockDim.x)
        atomicAdd(&counts[rows[i]], 1);
}

// per-block exclusive scan of counts into rowptr; block totals into bsums
__global__ void scan_block_k(const int* __restrict__ counts, int* rowptr, int* bsums, int n) {
    __shared__ int sh[1024];
    int tid = threadIdx.x;
    int i = blockIdx.x * 1024 + tid;
    int v = (i < n) ? counts[i] : 0;
    sh[tid] = v;
    __syncthreads();
    #pragma unroll
    for (int off = 1; off < 1024; off <<= 1) {
        int t = (tid >= off) ? sh[tid - off] : 0;
        __syncthreads();
        sh[tid] += t;
        __syncthreads();
    }
    if (i <= n) rowptr[i] = sh[tid] - v;     // exclusive within block (i==n gets block partial)
    if (tid == 1023) bsums[blockIdx.x] = sh[1023];
}

__global__ void scan_bsums_k(const int* __restrict__ bsums, int* bsums_ex, int nb) {
    __shared__ int sh[128];
    int tid = threadIdx.x;
    int v = (tid < nb) ? bsums[tid] : 0;
    sh[tid] = v;
    __syncthreads();
    #pragma unroll
    for (int off = 1; off < 128; off <<= 1) {
        int t = (tid >= off) ? sh[tid - off] : 0;
        __syncthreads();
        sh[tid] += t;
        __syncthreads();
    }
    if (tid < nb) bsums_ex[tid] = sh[tid] - v;
}

__global__ void add_offsets_k(int* rowptr, const int* __restrict__ bsums_ex, int n) {
    int i = blockIdx.x * 1024 + threadIdx.x;
    if (i <= n) rowptr[i] += bsums_ex[blockIdx.x];
}

__global__ void copy_cursor_k(const int* __restrict__ rowptr, int* cursor, int n) {
    for (int i = blockIdx.x * blockDim.x + threadIdx.x; i < n; i += gridDim.x * blockDim.x)
        cursor[i] = rowptr[i];
}

__global__ void scatter_k(const int* __restrict__ rows, const int* __restrict__ cols,
                          const float* __restrict__ vals, int* cursor,
                          int* ci, float* cv, int e) {
    for (int i = blockIdx.x * blockDim.x + threadIdx.x; i < e; i += gridDim.x * blockDim.x) {
        int r = rows[i];
        int p = atomicAdd(&cursor[r], 1);
        ci[p] = cols[i];
        cv[p] = vals[i];
    }
}

// ---------------- SGEMM: C[M,Nc] = A[M,K] @ B[K,Nc] (row-major, optional relu on A)
#define BM 128
#define BN 64
#define BK 16
#define TM 8
#define TN 4

template<bool RELU_A>
__global__ __launch_bounds__(256)
void sgemm_k(const float* __restrict__ A, const float* __restrict__ B,
             float* __restrict__ C, int M, int K, int Nc) {
    __shared__ float As[BK][BM + 4];
    __shared__ float Bs[BK][BN + 4];
    int tid = threadIdx.x;
    int bm = blockIdx.y * BM;
    int bn = blockIdx.x * BN;
    int tx = tid & 15;   // 0..15, n direction
    int ty = tid >> 4;   // 0..15, m direction

    float acc[TM][TN];
    #pragma unroll
    for (int i = 0; i < TM; i++)
        #pragma unroll
        for (int j = 0; j < TN; j++) acc[i][j] = 0.f;

    for (int k0 = 0; k0 < K; k0 += BK) {
        // load A tile: 128x16 = 512 float4, 2 per thread (transposed into smem)
        #pragma unroll
        for (int l = 0; l < 2; l++) {
            int f = tid * 2 + l;
            int m = f >> 2;
            int kq = (f & 3) * 4;
            int row = bm + m;
            float4 v = make_float4(0.f, 0.f, 0.f, 0.f);
            if (row < M) v = *(const float4*)(A + (size_t)row * K + k0 + kq);
            if (RELU_A) {
                v.x = fmaxf(v.x, 0.f); v.y = fmaxf(v.y, 0.f);
                v.z = fmaxf(v.z, 0.f); v.w = fmaxf(v.w, 0.f);
            }
            As[kq + 0][m] = v.x; As[kq + 1][m] = v.y;
            As[kq + 2][m] = v.z; As[kq + 3][m] = v.w;
        }
        // load B tile: 16x64 = 256 float4, 1 per thread
        {
            int kb = tid >> 4;
            int nb = (tid & 15) * 4;
            float4 v = *(const float4*)(B + (size_t)(k0 + kb) * Nc + bn + nb);
            *(float4*)&Bs[kb][nb] = v;
        }
        __syncthreads();
        #pragma unroll
        for (int k = 0; k < BK; k++) {
            float a[TM], b[TN];
            #pragma unroll
            for (int i = 0; i < TM; i++) a[i] = As[k][ty * TM + i];
            #pragma unroll
            for (int j = 0; j < TN; j++) b[j] = Bs[k][tx * TN + j];
            #pragma unroll
            for (int i = 0; i < TM; i++)
                #pragma unroll
                for (int j = 0; j < TN; j++) acc[i][j] = fmaf(a[i], b[j], acc[i][j]);
        }
        __syncthreads();
    }
    #pragma unroll
    for (int i = 0; i < TM; i++) {
        int row = bm + ty * TM + i;
        if (row < M) {
            float4 v = make_float4(acc[i][0], acc[i][1], acc[i][2], acc[i][3]);
            *(float4*)(C + (size_t)row * Nc + bn + tx * TN) = v;
        }
    }
}

// ---------------- SpMM (CSR gather): out[r,:] = sum_e val*H[col,:] + bias -----
template<int DIM, int TPB>
__global__ __launch_bounds__(TPB)
void spmm_k(const int* __restrict__ rp, const int* __restrict__ ci,
            const float* __restrict__ cv, const float* __restrict__ H,
            const float* __restrict__ bias, float* __restrict__ out) {
    constexpr int VPT = DIM / TPB;
    int row = blockIdx.x;
    int d = threadIdx.x;
    float acc[VPT];
    #pragma unroll
    for (int j = 0; j < VPT; j++) acc[j] = 0.f;
    int s = __ldg(rp + row);
    int e = __ldg(rp + row + 1);
    #pragma unroll 2
    for (int i = s; i < e; i++) {
        int c = __ldg(ci + i);
        float v = __ldg(cv + i);
        const float* hr = H + (size_t)c * DIM;
        #pragma unroll
        for (int j = 0; j < VPT; j++)
            acc[j] = fmaf(v, __ldg(hr + d + j * TPB), acc[j]);
    }
    #pragma unroll
    for (int j = 0; j < VPT; j++)
        out[(size_t)row * DIM + d + j * TPB] = acc[j] + __ldg(bias + d + j * TPB);
}

// ---------------- BatchNorm over relu(X), C=256 -------------------------------
__global__ void bn_zero_k(float* sum, float* sumsq) {
    int c = threadIdx.x;
    sum[c] = 0.f;
    sumsq[c] = 0.f;
}

__global__ void bn_stats_k(const float* __restrict__ X, float* sum, float* sumsq, int nrows) {
    int c = threadIdx.x;  // 256 threads
    float s = 0.f, s2 = 0.f;
    for (int r = blockIdx.x; r < nrows; r += gridDim.x) {
        float v = fmaxf(X[(size_t)r * BN_C + c], 0.f);
        s += v;
        s2 = fmaf(v, v, s2);
    }
    atomicAdd(&sum[c], s);
    atomicAdd(&sumsq[c], s2);
}

__global__ void bn_final_k(const float* __restrict__ sum, const float* __restrict__ sumsq,
                           float* mean, float* inv, int nrows) {
    int c = threadIdx.x;
    float m = sum[c] / (float)nrows;
    float var = sumsq[c] / (float)nrows - m * m;
    mean[c] = m;
    inv[c] = rsqrtf(var + EPS);
}

__global__ void bn_norm_k(const float* __restrict__ X, float* __restrict__ Y,
                          const float* __restrict__ mean, const float* __restrict__ inv,
                          int nrows) {
    int c = threadIdx.x;
    float m = mean[c];
    float iv = inv[c];
    for (int r = blockIdx.x; r < nrows; r += gridDim.x) {
        float v = fmaxf(X[(size_t)r * BN_C + c], 0.f);
        Y[(size_t)r * BN_C + c] = (v - m) * iv;
    }
}

// ---------------- launch -------------------------------------------------------
extern "C" void kernel_launch(void* const* d_in, const int* in_sizes, int n_in,
                              void* d_out, int out_size) {
    const float* x    = (const float*)d_in[0];
    const int*   rows = (const int*)  d_in[1];
    const int*   cols = (const int*)  d_in[2];
    const float* vals = (const float*)d_in[3];
    const float* w0   = (const float*)d_in[4];
    const float* b0   = (const float*)d_in[5];
    const float* w1   = (const float*)d_in[6];
    const float* b1   = (const float*)d_in[7];
    const float* dw0  = (const float*)d_in[8];
    const float* db0  = (const float*)d_in[9];
    const float* dw1  = (const float*)d_in[10];
    const float* db1  = (const float*)d_in[11];

    float* out   = (float*)d_out;
    float* x_out = out;                         // N x 128
    float* x_rec = out + (size_t)NN * 128;      // N x 512

    const int E = in_sizes[1];
    const int M = NN;

    // scratch pointers (pure host-side queries; graph-capture safe)
    float *bufA, *bufB, *sum, *sumsq, *mean, *inv, *csr_val;
    int *rowptr, *cursor, *counts, *bsums, *bsums_ex, *csr_col;
    cudaGetSymbolAddress((void**)&bufA,     g_bufA);
    cudaGetSymbolAddress((void**)&bufB,     g_bufB);
    cudaGetSymbolAddress((void**)&rowptr,   g_rowptr);
    cudaGetSymbolAddress((void**)&cursor,   g_cursor);
    cudaGetSymbolAddress((void**)&counts,   g_counts);
    cudaGetSymbolAddress((void**)&bsums,    g_bsums);
    cudaGetSymbolAddress((void**)&bsums_ex, g_bsums_ex);
    cudaGetSymbolAddress((void**)&csr_col,  g_csr_col);
    cudaGetSymbolAddress((void**)&csr_val,  g_csr_val);
    cudaGetSymbolAddress((void**)&sum,      g_sum);
    cudaGetSymbolAddress((void**)&sumsq,    g_sumsq);
    cudaGetSymbolAddress((void**)&mean,     g_mean);
    cudaGetSymbolAddress((void**)&inv,      g_inv);

    // ---- CSR build ----
    zero_counts_k<<<cdiv(M, 256), 256>>>(counts, M);
    hist_k<<<cdiv(E, 256), 256>>>(rows, counts, E);
    int nblk = cdiv(M + 1, 1024);                       // 98
    scan_block_k<<<nblk, 1024>>>(counts, rowptr, bsums, M);
    scan_bsums_k<<<1, 128>>>(bsums, bsums_ex, nblk);
    add_offsets_k<<<nblk, 1024>>>(rowptr, bsums_ex, M);
    copy_cursor_k<<<cdiv(M, 256), 256>>>(rowptr, cursor, M);
    scatter_k<<<cdiv(E, 256), 256>>>(rows, cols, vals, cursor, csr_col, csr_val, E);

    const int gy = cdiv(M, BM);   // 782

    // ---- encoder ----
    // h0 = x @ w0   (K=512, Nc=256) -> bufA
    sgemm_k<false><<<dim3(256 / BN, gy), 256>>>(x, w0, bufA, M, 512, 256);
    // h = spmm(h0) + b0 -> bufB
    spmm_k<256, 256><<<M, 256>>>(rowptr, csr_col, csr_val, bufA, b0, bufB);
    // h = bn(relu(h)) -> bufA
    bn_zero_k<<<1, 256>>>(sum, sumsq);
    bn_stats_k<<<2048, 256>>>(bufB, sum, sumsq, M);
    bn_final_k<<<1, 256>>>(sum, sumsq, mean, inv, M);
    bn_norm_k<<<2048, 256>>>(bufB, bufA, mean, inv, M);
    // h1 = h @ w1   (K=256, Nc=128) -> bufB
    sgemm_k<false><<<dim3(128 / BN, gy), 256>>>(bufA, w1, bufB, M, 256, 128);
    // x_out = spmm(h1) + b1 -> d_out[0:N*128]
    spmm_k<128, 128><<<M, 128>>>(rowptr, csr_col, csr_val, bufB, b1, x_out);

    // ---- decoder ----
    // r2 = relu(x_out) @ dw0  (K=128, Nc=256) -> bufA
    sgemm_k<true><<<dim3(256 / BN, gy), 256>>>(x_out, dw0, bufA, M, 128, 256);
    // r = spmm(r2) + db0 -> bufB
    spmm_k<256, 256><<<M, 256>>>(rowptr, csr_col, csr_val, bufA, db0, bufB);
    // r = bn(relu(r)) -> bufA
    bn_zero_k<<<1, 256>>>(sum, sumsq);
    bn_stats_k<<<2048, 256>>>(bufB, sum, sumsq, M);
    bn_final_k<<<1, 256>>>(sum, sumsq, mean, inv, M);
    bn_norm_k<<<2048, 256>>>(bufB, bufA, mean, inv, M);
    // r3 = r @ dw1  (K=256, Nc=512) -> bufB
    sgemm_k<false><<<dim3(512 / BN, gy), 256>>>(bufA, dw1, bufB, M, 256, 512);
    // x_rec = spmm(r3) + db1 -> d_out[N*128:]
    spmm_k<512, 256><<<M, 256>>>(rowptr, csr_col, csr_val, bufB, db1, x_rec);
}

// round 17
// speedup vs baseline: 1.0698x; 1.0698x over previous
#include <cuda_runtime.h>
#include <cuda_bf16.h>
#include <math.h>
#include <stdint.h>

#define NN 100000
#define EE 3200000
#define BN_C 256
#define EPS 1e-5f

// ---------------- scratch (device globals; no allocation allowed) -------------
__device__ float g_bufA[(size_t)NN * 512];
__device__ float g_bufB[(size_t)NN * 512];
__device__ int   g_rowptr[NN + 1];
__device__ int   g_cursor[NN];
__device__ int   g_counts[NN];
__device__ int   g_bsums[128];
__device__ int   g_bsums_ex[128];
__device__ int   g_csr_col[EE];
__device__ float g_csr_val[EE];
__device__ float g_sum[BN_C];
__device__ float g_sumsq[BN_C];
__device__ float g_mean[BN_C];
__device__ float g_inv[BN_C];

static inline int cdiv(int a, int b) { return (a + b - 1) / b; }

// ---------------- CSR build ---------------------------------------------------
__global__ void zero_counts_k(int* counts, int n) {
    for (int i = blockIdx.x * blockDim.x + threadIdx.x; i < n; i += gridDim.x * blockDim.x)
        counts[i] = 0;
}

__global__ void hist_k(const int* __restrict__ rows, int* counts, int e) {
    for (int i = blockIdx.x * blockDim.x + threadIdx.x; i < e; i += gridDim.x * blockDim.x)
        atomicAdd(&counts[rows[i]], 1);
}

__global__ void scan_block_k(const int* __restrict__ counts, int* rowptr, int* bsums, int n) {
    __shared__ int sh[1024];
    int tid = threadIdx.x;
    int i = blockIdx.x * 1024 + tid;
    int v = (i < n) ? counts[i] : 0;
    sh[tid] = v;
    __syncthreads();
    #pragma unroll
    for (int off = 1; off < 1024; off <<= 1) {
        int t = (tid >= off) ? sh[tid - off] : 0;
        __syncthreads();
        sh[tid] += t;
        __syncthreads();
    }
    if (i <= n) rowptr[i] = sh[tid] - v;
    if (tid == 1023) bsums[blockIdx.x] = sh[1023];
}

__global__ void scan_bsums_k(const int* __restrict__ bsums, int* bsums_ex, int nb) {
    __shared__ int sh[128];
    int tid = threadIdx.x;
    int v = (tid < nb) ? bsums[tid] : 0;
    sh[tid] = v;
    __syncthreads();
    #pragma unroll
    for (int off = 1; off < 128; off <<= 1) {
        int t = (tid >= off) ? sh[tid - off] : 0;
        __syncthreads();
        sh[tid] += t;
        __syncthreads();
    }
    if (tid < nb) bsums_ex[tid] = sh[tid] - v;
}

__global__ void add_offsets_k(int* rowptr, const int* __restrict__ bsums_ex, int n) {
    int i = blockIdx.x * 1024 + threadIdx.x;
    if (i <= n) rowptr[i] += bsums_ex[blockIdx.x];
}

__global__ void copy_cursor_k(const int* __restrict__ rowptr, int* cursor, int n) {
    for (int i = blockIdx.x * blockDim.x + threadIdx.x; i < n; i += gridDim.x * blockDim.x)
        cursor[i] = rowptr[i];
}

__global__ void scatter_k(const int* __restrict__ rows, const int* __restrict__ cols,
                          const float* __restrict__ vals, int* cursor,
                          int* ci, float* cv, int e) {
    for (int i = blockIdx.x * blockDim.x + threadIdx.x; i < e; i += gridDim.x * blockDim.x) {
        int r = rows[i];
        int p = atomicAdd(&cursor[r], 1);
        ci[p] = cols[i];
        cv[p] = vals[i];
    }
}

// ---------------- 3xTF32 tensor-core GEMM (fp32-accurate) ---------------------
// C[M,Nc] = A[M,K] @ B[K,Nc], row-major. Optional relu on A.
// Each operand split x = hi + lo (hi = tf32(x), lo = tf32(x - hi));
// product = aH*bH + aH*bL + aL*bH  (lo*lo dropped, <= 2^-22 * |a||b|).
// CTA tile 128x64, BK=16, 256 threads = 8 warps (4 M x 2 N),
// warp tile 32x32 via 2x4 m16n8k8 fragments, 3 mmas each.
// smem strides: A=20 words, B=72 words -> conflict-free fragment loads.

__device__ __forceinline__ uint32_t f2tf(float x) {
    uint32_t r;
    asm("cvt.rna.tf32.f32 %0, %1;" : "=r"(r) : "f"(x));
    return r;
}

__device__ __forceinline__ void split_tf(float x, uint32_t& h, uint32_t& l) {
    h = f2tf(x);
    l = f2tf(x - __uint_as_float(h));
}

__device__ __forceinline__ void mma_tf32(float* d, const uint32_t* a, const uint32_t* b) {
    asm volatile(
        "mma.sync.aligned.m16n8k8.row.col.f32.tf32.tf32.f32 "
        "{%0,%1,%2,%3}, {%4,%5,%6,%7}, {%8,%9}, {%0,%1,%2,%3};"
        : "+f"(d[0]), "+f"(d[1]), "+f"(d[2]), "+f"(d[3])
        : "r"(a[0]), "r"(a[1]), "r"(a[2]), "r"(a[3]), "r"(b[0]), "r"(b[1]));
}

template<bool RELU_A>
__global__ __launch_bounds__(256)
void tf32gemm3_k(const float* __restrict__ A, const float* __restrict__ B,
                 float* __restrict__ C, int M, int K, int Nc) {
    __shared__ uint32_t AsH[128 * 20];
    __shared__ uint32_t AsL[128 * 20];
    __shared__ uint32_t BsH[16 * 72];
    __shared__ uint32_t BsL[16 * 72];

    const int tid = threadIdx.x;
    const int lane = tid & 31;
    const int wid = tid >> 5;
    const int bm = blockIdx.y * 128;
    const int bn = blockIdx.x * 64;
    const int wm = (wid & 3) * 32;
    const int wn = (wid >> 2) * 32;

    float acc[2][4][4];
    #pragma unroll
    for (int i = 0; i < 2; i++)
        #pragma unroll
        for (int j = 0; j < 4; j++)
            #pragma unroll
            for (int r = 0; r < 4; r++) acc[i][j][r] = 0.f;

    // A staging: thread -> row tid>>1, 8 consecutive k at (tid&1)*8
    const int am = tid >> 1;
    const int akq = (tid & 1) * 8;
    const int arow = bm + am;
    // B staging: thread -> k row tid>>4, 4 consecutive n at (tid&15)*4
    const int bkr = tid >> 4;
    const int bnc = (tid & 15) * 4;

    float ra[8], rbv[4];

    auto loadTile = [&](int k0) {
        #pragma unroll
        for (int j = 0; j < 8; j++) ra[j] = 0.f;
        if (arow < M) {
            float4 v0 = *(const float4*)(A + (size_t)arow * K + k0 + akq);
            float4 v1 = *(const float4*)(A + (size_t)arow * K + k0 + akq + 4);
            ra[0] = v0.x; ra[1] = v0.y; ra[2] = v0.z; ra[3] = v0.w;
            ra[4] = v1.x; ra[5] = v1.y; ra[6] = v1.z; ra[7] = v1.w;
        }
        if (RELU_A) {
            #pragma unroll
            for (int j = 0; j < 8; j++) ra[j] = fmaxf(ra[j], 0.f);
        }
        float4 vb = *(const float4*)(B + (size_t)(k0 + bkr) * Nc + bn + bnc);
        rbv[0] = vb.x; rbv[1] = vb.y; rbv[2] = vb.z; rbv[3] = vb.w;
    };

    auto storeTile = [&]() {
        uint32_t h[8], l[8];
        #pragma unroll
        for (int j = 0; j < 8; j++) split_tf(ra[j], h[j], l[j]);
        *(uint4*)&AsH[am * 20 + akq]     = make_uint4(h[0], h[1], h[2], h[3]);
        *(uint4*)&AsH[am * 20 + akq + 4] = make_uint4(h[4], h[5], h[6], h[7]);
        *(uint4*)&AsL[am * 20 + akq]     = make_uint4(l[0], l[1], l[2], l[3]);
        *(uint4*)&AsL[am * 20 + akq + 4] = make_uint4(l[4], l[5], l[6], l[7]);
        uint32_t bh[4], bl[4];
        #pragma unroll
        for (int j = 0; j < 4; j++) split_tf(rbv[j], bh[j], bl[j]);
        *(uint4*)&BsH[bkr * 72 + bnc] = make_uint4(bh[0], bh[1], bh[2], bh[3]);
        *(uint4*)&BsL[bkr * 72 + bnc] = make_uint4(bl[0], bl[1], bl[2], bl[3]);
    };

    // prologue
    loadTile(0);
    storeTile();
    __syncthreads();

    const int nk = K >> 4;
    const int ar = lane >> 2;
    const int ac = lane & 3;

    for (int it = 0; it < nk; it++) {
        const bool have_next = (it + 1 < nk);
        if (have_next) loadTile((it + 1) * 16);

        #pragma unroll
        for (int kk = 0; kk < 16; kk += 8) {
            uint32_t afh[2][4], afl[2][4];
            #pragma unroll
            for (int tm = 0; tm < 2; tm++) {
                const int r0 = wm + tm * 16 + ar;
                const int i00 = r0 * 20 + kk + ac;
                const int i10 = (r0 + 8) * 20 + kk + ac;
                afh[tm][0] = AsH[i00];     afl[tm][0] = AsL[i00];
                afh[tm][1] = AsH[i10];     afl[tm][1] = AsL[i10];
                afh[tm][2] = AsH[i00 + 4]; afl[tm][2] = AsL[i00 + 4];
                afh[tm][3] = AsH[i10 + 4]; afl[tm][3] = AsL[i10 + 4];
            }
            uint32_t bfh[4][2], bfl[4][2];
            #pragma unroll
            for (int tn = 0; tn < 4; tn++) {
                const int c = wn + tn * 8 + ar;
                const int j0 = (kk + ac) * 72 + c;
                const int j1 = (kk + ac + 4) * 72 + c;
                bfh[tn][0] = BsH[j0]; bfl[tn][0] = BsL[j0];
                bfh[tn][1] = BsH[j1]; bfl[tn][1] = BsL[j1];
            }
            #pragma unroll
            for (int tm = 0; tm < 2; tm++)
                #pragma unroll
                for (int tn = 0; tn < 4; tn++) {
                    mma_tf32(acc[tm][tn], afh[tm], bfl[tn]);
                    mma_tf32(acc[tm][tn], afl[tm], bfh[tn]);
                    mma_tf32(acc[tm][tn], afh[tm], bfh[tn]);
                }
        }

        if (have_next) {
            __syncthreads();
            storeTile();
            __syncthreads();
        }
    }

    // epilogue
    const int ac2 = (lane & 3) * 2;
    #pragma unroll
    for (int tm = 0; tm < 2; tm++) {
        const int r0 = bm + wm + tm * 16 + ar;
        #pragma unroll
        for (int tn = 0; tn < 4; tn++) {
            const int c = bn + wn + tn * 8 + ac2;
            if (r0 < M)
                *(float2*)(C + (size_t)r0 * Nc + c) = make_float2(acc[tm][tn][0], acc[tm][tn][1]);
            if (r0 + 8 < M)
                *(float2*)(C + (size_t)(r0 + 8) * Nc + c) = make_float2(acc[tm][tn][2], acc[tm][tn][3]);
        }
    }
}

// ---------------- SpMM (CSR gather): out[r,:] = sum_e val*H[col,:] + bias -----
template<int DIM, int TPB>
__global__ __launch_bounds__(TPB)
void spmm_k(const int* __restrict__ rp, const int* __restrict__ ci,
            const float* __restrict__ cv, const float* __restrict__ H,
            const float* __restrict__ bias, float* __restrict__ out) {
    constexpr int VPT = DIM / TPB;
    int row = blockIdx.x;
    int d = threadIdx.x;
    float acc[VPT];
    #pragma unroll
    for (int j = 0; j < VPT; j++) acc[j] = 0.f;
    int s = __ldg(rp + row);
    int e = __ldg(rp + row + 1);
    #pragma unroll 2
    for (int i = s; i < e; i++) {
        int c = __ldg(ci + i);
        float v = __ldg(cv + i);
        const float* hr = H + (size_t)c * DIM;
        #pragma unroll
        for (int j = 0; j < VPT; j++)
            acc[j] = fmaf(v, __ldg(hr + d + j * TPB), acc[j]);
    }
    #pragma unroll
    for (int j = 0; j < VPT; j++)
        out[(size_t)row * DIM + d + j * TPB] = acc[j] + __ldg(bias + d + j * TPB);
}

// ---------------- BatchNorm over relu(X), C=256 -------------------------------
__global__ void bn_zero_k(float* sum, float* sumsq) {
    int c = threadIdx.x;
    sum[c] = 0.f;
    sumsq[c] = 0.f;
}

__global__ void bn_stats_k(const float* __restrict__ X, float* sum, float* sumsq, int nrows) {
    int c = threadIdx.x;
    float s = 0.f, s2 = 0.f;
    for (int r = blockIdx.x; r < nrows; r += gridDim.x) {
        float v = fmaxf(X[(size_t)r * BN_C + c], 0.f);
        s += v;
        s2 = fmaf(v, v, s2);
    }
    atomicAdd(&sum[c], s);
    atomicAdd(&sumsq[c], s2);
}

__global__ void bn_final_k(const float* __restrict__ sum, const float* __restrict__ sumsq,
                           float* mean, float* inv, int nrows) {
    int c = threadIdx.x;
    float m = sum[c] / (float)nrows;
    float var = sumsq[c] / (float)nrows - m * m;
    mean[c] = m;
    inv[c] = rsqrtf(var + EPS);
}

__global__ void bn_norm_k(const float* __restrict__ X, float* __restrict__ Y,
                          const float* __restrict__ mean, const float* __restrict__ inv,
                          int nrows) {
    int c = threadIdx.x;
    float m = mean[c];
    float iv = inv[c];
    for (int r = blockIdx.x; r < nrows; r += gridDim.x) {
        float v = fmaxf(X[(size_t)r * BN_C + c], 0.f);
        Y[(size_t)r * BN_C + c] = (v - m) * iv;
    }
}

// ---------------- launch -------------------------------------------------------
extern "C" void kernel_launch(void* const* d_in, const int* in_sizes, int n_in,
                              void* d_out, int out_size) {
    const float* x    = (const float*)d_in[0];
    const int*   rows = (const int*)  d_in[1];
    const int*   cols = (const int*)  d_in[2];
    const float* vals = (const float*)d_in[3];
    const float* w0   = (const float*)d_in[4];
    const float* b0   = (const float*)d_in[5];
    const float* w1   = (const float*)d_in[6];
    const float* b1   = (const float*)d_in[7];
    const float* dw0  = (const float*)d_in[8];
    const float* db0  = (const float*)d_in[9];
    const float* dw1  = (const float*)d_in[10];
    const float* db1  = (const float*)d_in[11];

    float* out   = (float*)d_out;
    float* x_out = out;                         // N x 128
    float* x_rec = out + (size_t)NN * 128;      // N x 512

    const int E = in_sizes[1];
    const int M = NN;

    float *bufA, *bufB, *sum, *sumsq, *mean, *inv, *csr_val;
    int *rowptr, *cursor, *counts, *bsums, *bsums_ex, *csr_col;
    cudaGetSymbolAddress((void**)&bufA,     g_bufA);
    cudaGetSymbolAddress((void**)&bufB,     g_bufB);
    cudaGetSymbolAddress((void**)&rowptr,   g_rowptr);
    cudaGetSymbolAddress((void**)&cursor,   g_cursor);
    cudaGetSymbolAddress((void**)&counts,   g_counts);
    cudaGetSymbolAddress((void**)&bsums,    g_bsums);
    cudaGetSymbolAddress((void**)&bsums_ex, g_bsums_ex);
    cudaGetSymbolAddress((void**)&csr_col,  g_csr_col);
    cudaGetSymbolAddress((void**)&csr_val,  g_csr_val);
    cudaGetSymbolAddress((void**)&sum,      g_sum);
    cudaGetSymbolAddress((void**)&sumsq,    g_sumsq);
    cudaGetSymbolAddress((void**)&mean,     g_mean);
    cudaGetSymbolAddress((void**)&inv,      g_inv);

    // ---- CSR build ----
    zero_counts_k<<<cdiv(M, 256), 256>>>(counts, M);
    hist_k<<<cdiv(E, 256), 256>>>(rows, counts, E);
    int nblk = cdiv(M + 1, 1024);
    scan_block_k<<<nblk, 1024>>>(counts, rowptr, bsums, M);
    scan_bsums_k<<<1, 128>>>(bsums, bsums_ex, nblk);
    add_offsets_k<<<nblk, 1024>>>(rowptr, bsums_ex, M);
    copy_cursor_k<<<cdiv(M, 256), 256>>>(rowptr, cursor, M);
    scatter_k<<<cdiv(E, 256), 256>>>(rows, cols, vals, cursor, csr_col, csr_val, E);

    const int gy = cdiv(M, 128);   // 782

    // ---- encoder ----
    tf32gemm3_k<false><<<dim3(256 / 64, gy), 256>>>(x, w0, bufA, M, 512, 256);
    spmm_k<256, 256><<<M, 256>>>(rowptr, csr_col, csr_val, bufA, b0, bufB);
    bn_zero_k<<<1, 256>>>(sum, sumsq);
    bn_stats_k<<<2048, 256>>>(bufB, sum, sumsq, M);
    bn_final_k<<<1, 256>>>(sum, sumsq, mean, inv, M);
    bn_norm_k<<<2048, 256>>>(bufB, bufA, mean, inv, M);
    tf32gemm3_k<false><<<dim3(128 / 64, gy), 256>>>(bufA, w1, bufB, M, 256, 128);
    spmm_k<128, 128><<<M, 128>>>(rowptr, csr_col, csr_val, bufB, b1, x_out);

    // ---- decoder ----
    tf32gemm3_k<true><<<dim3(256 / 64, gy), 256>>>(x_out, dw0, bufA, M, 128, 256);
    spmm_k<256, 256><<<M, 256>>>(rowptr, csr_col, csr_val, bufA, db0, bufB);
    bn_zero_k<<<1, 256>>>(sum, sumsq);
    bn_stats_k<<<2048, 256>>>(bufB, sum, sumsq, M);
    bn_final_k<<<1, 256>>>(sum, sumsq, mean, inv, M);
    bn_norm_k<<<2048, 256>>>(bufB, bufA, mean, inv, M);
    tf32gemm3_k<false><<<dim3(512 / 64, gy), 256>>>(bufA, dw1, bufB, M, 256, 512);
    spmm_k<512, 256><<<M, 256>>>(rowptr, csr_col, csr_val, bufB, db1, x_rec);
}